// round 13
// baseline (speedup 1.0000x reference)
#include <cuda_runtime.h>
#include <cuda_bf16.h>

#define N_NODES 50000
#define N_EDGES 800000
#define D 64
#define NB 64                 // nodes per layer-block
#define SP 68                 // shared activation row pitch (floats); %4==0 for float4, %32==4 spreads banks
#define NBLK_SCAN ((N_NODES + 1023) / 1024)   // 49

// ---------------- device scratch (no allocation allowed) ----------------
__device__ int   g_is64;                  // runtime-detected edge_index dtype flag
__device__ int   g_count[N_NODES];
__device__ int   g_off[N_NODES + 1];
__device__ int   g_cursor[N_NODES];       // also scan temp
__device__ int   g_bsum[NBLK_SCAN];
__device__ int   g_bpre[NBLK_SCAN];
__device__ int2  g_edge[N_EDGES];         // (src, weight-as-int), sorted by dst
__device__ float g_buf1[N_NODES * D];     // layer-1 output
__device__ float g_W1T[2][D * D];         // W1T[k*D + o] = W1[o*D + k]
__device__ float g_W2T[2][D * D];

// ---------------- packed f32x2 FMA (sm_103a) with scalar fallback ----------------
union F2 { unsigned long long u; float2 f; };

__device__ __forceinline__ unsigned long long ffma2u(unsigned long long a,
                                                     unsigned long long b,
                                                     unsigned long long c) {
#if defined(__CUDA_ARCH__) && (__CUDA_ARCH__ >= 1000)
    unsigned long long d;
    asm("fma.rn.f32x2 %0, %1, %2, %3;" : "=l"(d) : "l"(a), "l"(b), "l"(c));
    return d;
#else
    F2 fa, fb, fc, fd;
    fa.u = a; fb.u = b; fc.u = c;
    fd.f.x = fmaf(fa.f.x, fb.f.x, fc.f.x);
    fd.f.y = fmaf(fa.f.y, fb.f.y, fc.f.y);
    return fd.u;
#endif
}

// ---------------- edge dtype detection ----------------
// If edge_index is int64 (LE) with node values in [0, 50000), every odd 32-bit
// word is a zero high-word. If int32, odd words are uniform indices: P(64 zeros)
// ~ (1/50000)^64 ~ 0. Deterministic, reads only the first 512 bytes (safe for
// both dtypes: int32 buffer is 6.4 MB).
__global__ void k_detect(const unsigned int* __restrict__ ei32) {
    if (threadIdx.x == 0 && blockIdx.x == 0) {
        int allzero = 1;
        #pragma unroll 1
        for (int i = 0; i < 64; i++)
            if (ei32[2 * i + 1] != 0u) { allzero = 0; break; }
        g_is64 = allzero;
    }
}

__device__ __forceinline__ int load_idx(const int* __restrict__ ei, long long pos, int is64) {
    int v;
    if (is64) v = (int)((const long long*)ei)[pos];
    else      v = ei[pos];
    // clamp: a wrong decode becomes a wrong answer (rel_err signal), not a crash
    v = v < 0 ? 0 : (v >= N_NODES ? N_NODES - 1 : v);
    return v;
}

// ---------------- prep: zero histogram counts + transpose weights (independent work, one launch) ----------------
__global__ void k_prep(const float* __restrict__ W10, const float* __restrict__ W20,
                       const float* __restrict__ W11, const float* __restrict__ W21) {
    int i = blockIdx.x * blockDim.x + threadIdx.x;
    if (i < N_NODES) g_count[i] = 0;
    if (i < D * D) {
        int o = i / D, k = i % D;
        g_W1T[0][k * D + o] = W10[i];
        g_W2T[0][k * D + o] = W20[i];
        g_W1T[1][k * D + o] = W11[i];
        g_W2T[1][k * D + o] = W21[i];
    }
}

// ---------------- CSR build ----------------
__global__ void k_hist(const int* __restrict__ ei) {
    int e = blockIdx.x * blockDim.x + threadIdx.x;
    if (e < N_EDGES) {
        int is64 = g_is64;
        int d = load_idx(ei, (long long)N_EDGES + e, is64);
        atomicAdd(&g_count[d], 1);
    }
}

// grid scan stage 1: per-block inclusive scan -> g_cursor (temp) + block sums
__global__ void k_scan1() {
    __shared__ int sh[1024];
    int t = threadIdx.x, b = blockIdx.x;
    int i = b * 1024 + t;
    int v = (i < N_NODES) ? g_count[i] : 0;
    sh[t] = v;
    __syncthreads();
    #pragma unroll
    for (int ofs = 1; ofs < 1024; ofs <<= 1) {
        int u = (t >= ofs) ? sh[t - ofs] : 0;
        __syncthreads();
        sh[t] += u;
        __syncthreads();
    }
    if (i < N_NODES) g_cursor[i] = sh[t];
    if (t == 1023) g_bsum[b] = sh[t];
}

// stage 2: parallel exclusive scan of NBLK_SCAN block sums (64-thread Hillis-Steele)
__global__ void k_scan2() {
    __shared__ int sh[64];
    int t = threadIdx.x;
    int v = (t < NBLK_SCAN) ? g_bsum[t] : 0;
    sh[t] = v;
    __syncthreads();
    #pragma unroll
    for (int ofs = 1; ofs < 64; ofs <<= 1) {
        int u = (t >= ofs) ? sh[t - ofs] : 0;
        __syncthreads();
        sh[t] += u;
        __syncthreads();
    }
    if (t < NBLK_SCAN) g_bpre[t] = sh[t] - v;   // exclusive
}

// stage 3: global exclusive offsets + scatter cursor
__global__ void k_scan3() {
    int t = threadIdx.x, b = blockIdx.x;
    int i = b * 1024 + t;
    if (i < N_NODES) {
        int excl = g_bpre[b] + g_cursor[i] - g_count[i];
        g_off[i] = excl;
        g_cursor[i] = excl;
    }
    if (i == 0) g_off[N_NODES] = N_EDGES;
}

__global__ void k_scatter(const int* __restrict__ ei,
                          const float* __restrict__ w) {
    int e = blockIdx.x * blockDim.x + threadIdx.x;
    if (e < N_EDGES) {
        int is64 = g_is64;
        int d = load_idx(ei, (long long)N_EDGES + e, is64);
        int s = load_idx(ei, e, is64);
        int p = atomicAdd(&g_cursor[d], 1);
        g_edge[p] = make_int2(s, __float_as_int(w[e]));
    }
}

// ---------------- fused GIN layer ----------------
// Block = 256 threads, NB = 64 nodes. smem = 50176 B; __launch_bounds__(256,4) forces
// regs <= 64/thread so 4 blocks/SM (32 warps) is guaranteed, not incidental.
// Phase A (gather): 8 warps x 8 nodes each; warp-coalesced float2 row gather, x4 edge unroll (MLP=4).
// Phase B (MLP): thread (tg = tid>>3: node pair, tt = tid&7: feature octet).
//   Feature-paired FFMA2: weight pairs fall out of LDS.128 float4s as adjacent register
//   pairs (free); activation splat is 2 alu movs/k. 8 FFMA2 per k per thread.
//   sA is reused for the hidden activations (extra barrier instead of a second buffer).
template <bool NORM>
__global__ void __launch_bounds__(256, 4) k_layer(const float* __restrict__ xin,
                                                  float* __restrict__ xout,
                                                  const float* __restrict__ W1T,
                                                  const float* __restrict__ W2T) {
    extern __shared__ float smem[];
    float* sW1 = smem;                  // 4096 floats
    float* sW2 = smem + 4096;           // 4096
    float* sA  = smem + 8192;           // NB*SP floats (agg, then reused for h)

    int tid = threadIdx.x;
    int base = blockIdx.x * NB;

    // stage weights (float4 copies) — covered by the barrier after Phase A
    {
        const float4* w1 = (const float4*)W1T;
        const float4* w2 = (const float4*)W2T;
        float4* s1 = (float4*)sW1;
        float4* s2 = (float4*)sW2;
        #pragma unroll
        for (int i = tid; i < (D * D) / 4; i += 256) {
            s1[i] = w1[i];
            s2[i] = w2[i];
        }
    }

    // ---- Phase A: weighted gather-sum ----
    {
        int warp = tid >> 5;
        int lane = tid & 31;
        #pragma unroll 1
        for (int n = 0; n < 8; n++) {
            int ln = warp * 8 + n;
            int node = base + ln;
            float a0 = 0.f, a1 = 0.f;
            if (node < N_NODES) {
                int beg = g_off[node];
                int end = g_off[node + 1];
                int e = beg;
                const float* xp = xin + (size_t)lane * 2;
                for (; e + 4 <= end; e += 4) {
                    int2 e0 = g_edge[e + 0];
                    int2 e1 = g_edge[e + 1];
                    int2 e2 = g_edge[e + 2];
                    int2 e3 = g_edge[e + 3];
                    float2 x0 = *(const float2*)(xp + (size_t)e0.x * D);
                    float2 x1 = *(const float2*)(xp + (size_t)e1.x * D);
                    float2 x2 = *(const float2*)(xp + (size_t)e2.x * D);
                    float2 x3 = *(const float2*)(xp + (size_t)e3.x * D);
                    a0 += __int_as_float(e0.y) * x0.x; a1 += __int_as_float(e0.y) * x0.y;
                    a0 += __int_as_float(e1.y) * x1.x; a1 += __int_as_float(e1.y) * x1.y;
                    a0 += __int_as_float(e2.y) * x2.x; a1 += __int_as_float(e2.y) * x2.y;
                    a0 += __int_as_float(e3.y) * x3.x; a1 += __int_as_float(e3.y) * x3.y;
                }
                for (; e < end; e++) {
                    int2 ed = g_edge[e];
                    float2 xv = *(const float2*)(xp + (size_t)ed.x * D);
                    a0 += __int_as_float(ed.y) * xv.x;
                    a1 += __int_as_float(ed.y) * xv.y;
                }
            }
            // single 64-bit STS (8-byte aligned: ln*SP even, lane*2 even)
            *(float2*)(sA + ln * SP + lane * 2) = make_float2(a0, a1);
        }
    }
    __syncthreads();

    // ---- Phase B: FFMA2-tiled MLP (2 nodes x 8 features per thread) ----
    int tg = tid >> 3;        // node pair 0..31 -> nodes 2tg, 2tg+1
    int tt = tid & 7;         // feature octet 0..7 -> features 8tt..8tt+7
    int rowA = 2 * tg * SP;   // node0 activation row
    int wcol = tt * 8;

    F2 acc0[4], acc1[4];
    #pragma unroll
    for (int p = 0; p < 4; p++) { acc0[p].u = 0ull; acc1[p].u = 0ull; }

    // h = relu(agg @ W1^T)
    #pragma unroll 8
    for (int k = 0; k < D; k++) {
        float a0 = sA[rowA + k];
        float a1 = sA[rowA + SP + k];
        F2 as0, as1;
        as0.f = make_float2(a0, a0);
        as1.f = make_float2(a1, a1);
        float4 w0 = *(const float4*)(sW1 + k * D + wcol);
        float4 w1 = *(const float4*)(sW1 + k * D + wcol + 4);
        F2 wp0, wp1, wp2, wp3;
        wp0.f = make_float2(w0.x, w0.y);
        wp1.f = make_float2(w0.z, w0.w);
        wp2.f = make_float2(w1.x, w1.y);
        wp3.f = make_float2(w1.z, w1.w);
        acc0[0].u = ffma2u(as0.u, wp0.u, acc0[0].u);
        acc0[1].u = ffma2u(as0.u, wp1.u, acc0[1].u);
        acc0[2].u = ffma2u(as0.u, wp2.u, acc0[2].u);
        acc0[3].u = ffma2u(as0.u, wp3.u, acc0[3].u);
        acc1[0].u = ffma2u(as1.u, wp0.u, acc1[0].u);
        acc1[1].u = ffma2u(as1.u, wp1.u, acc1[1].u);
        acc1[2].u = ffma2u(as1.u, wp2.u, acc1[2].u);
        acc1[3].u = ffma2u(as1.u, wp3.u, acc1[3].u);
    }

    // all threads done READING sA before it is overwritten with h
    __syncthreads();

    // relu + stage h back into sA
    {
        float4 h0a = make_float4(fmaxf(acc0[0].f.x, 0.f), fmaxf(acc0[0].f.y, 0.f),
                                 fmaxf(acc0[1].f.x, 0.f), fmaxf(acc0[1].f.y, 0.f));
        float4 h0b = make_float4(fmaxf(acc0[2].f.x, 0.f), fmaxf(acc0[2].f.y, 0.f),
                                 fmaxf(acc0[3].f.x, 0.f), fmaxf(acc0[3].f.y, 0.f));
        float4 h1a = make_float4(fmaxf(acc1[0].f.x, 0.f), fmaxf(acc1[0].f.y, 0.f),
                                 fmaxf(acc1[1].f.x, 0.f), fmaxf(acc1[1].f.y, 0.f));
        float4 h1b = make_float4(fmaxf(acc1[2].f.x, 0.f), fmaxf(acc1[2].f.y, 0.f),
                                 fmaxf(acc1[3].f.x, 0.f), fmaxf(acc1[3].f.y, 0.f));
        *(float4*)(sA + rowA + wcol)          = h0a;
        *(float4*)(sA + rowA + wcol + 4)      = h0b;
        *(float4*)(sA + rowA + SP + wcol)     = h1a;
        *(float4*)(sA + rowA + SP + wcol + 4) = h1b;
    }
    __syncthreads();

    // o = h @ W2^T
    #pragma unroll
    for (int p = 0; p < 4; p++) { acc0[p].u = 0ull; acc1[p].u = 0ull; }
    #pragma unroll 8
    for (int k = 0; k < D; k++) {
        float a0 = sA[rowA + k];
        float a1 = sA[rowA + SP + k];
        F2 as0, as1;
        as0.f = make_float2(a0, a0);
        as1.f = make_float2(a1, a1);
        float4 w0 = *(const float4*)(sW2 + k * D + wcol);
        float4 w1 = *(const float4*)(sW2 + k * D + wcol + 4);
        F2 wp0, wp1, wp2, wp3;
        wp0.f = make_float2(w0.x, w0.y);
        wp1.f = make_float2(w0.z, w0.w);
        wp2.f = make_float2(w1.x, w1.y);
        wp3.f = make_float2(w1.z, w1.w);
        acc0[0].u = ffma2u(as0.u, wp0.u, acc0[0].u);
        acc0[1].u = ffma2u(as0.u, wp1.u, acc0[1].u);
        acc0[2].u = ffma2u(as0.u, wp2.u, acc0[2].u);
        acc0[3].u = ffma2u(as0.u, wp3.u, acc0[3].u);
        acc1[0].u = ffma2u(as1.u, wp0.u, acc1[0].u);
        acc1[1].u = ffma2u(as1.u, wp1.u, acc1[1].u);
        acc1[2].u = ffma2u(as1.u, wp2.u, acc1[2].u);
        acc1[3].u = ffma2u(as1.u, wp3.u, acc1[3].u);
    }

    int n0 = base + 2 * tg;
    int n1 = n0 + 1;

    if (NORM) {
        // per-node sum of squares over this thread's 8 features, then reduce
        // across the 8 contiguous tt-lanes (width-8 shuffle).
        float sq0 = acc0[0].f.x * acc0[0].f.x + acc0[0].f.y * acc0[0].f.y
                  + acc0[1].f.x * acc0[1].f.x + acc0[1].f.y * acc0[1].f.y
                  + acc0[2].f.x * acc0[2].f.x + acc0[2].f.y * acc0[2].f.y
                  + acc0[3].f.x * acc0[3].f.x + acc0[3].f.y * acc0[3].f.y;
        float sq1 = acc1[0].f.x * acc1[0].f.x + acc1[0].f.y * acc1[0].f.y
                  + acc1[1].f.x * acc1[1].f.x + acc1[1].f.y * acc1[1].f.y
                  + acc1[2].f.x * acc1[2].f.x + acc1[2].f.y * acc1[2].f.y
                  + acc1[3].f.x * acc1[3].f.x + acc1[3].f.y * acc1[3].f.y;
        #pragma unroll
        for (int m = 4; m > 0; m >>= 1) {
            sq0 += __shfl_xor_sync(0xffffffffu, sq0, m, 8);
            sq1 += __shfl_xor_sync(0xffffffffu, sq1, m, 8);
        }
        float inv0 = 1.f / fmaxf(sqrtf(sq0), 1e-12f);
        float inv1 = 1.f / fmaxf(sqrtf(sq1), 1e-12f);
        #pragma unroll
        for (int p = 0; p < 4; p++) {
            acc0[p].f.x *= inv0; acc0[p].f.y *= inv0;
            acc1[p].f.x *= inv1; acc1[p].f.y *= inv1;
        }
    }

    if (n0 < N_NODES) {
        *(float4*)(xout + (size_t)n0 * D + wcol) =
            make_float4(acc0[0].f.x, acc0[0].f.y, acc0[1].f.x, acc0[1].f.y);
        *(float4*)(xout + (size_t)n0 * D + wcol + 4) =
            make_float4(acc0[2].f.x, acc0[2].f.y, acc0[3].f.x, acc0[3].f.y);
    }
    if (n1 < N_NODES) {
        *(float4*)(xout + (size_t)n1 * D + wcol) =
            make_float4(acc1[0].f.x, acc1[0].f.y, acc1[1].f.x, acc1[1].f.y);
        *(float4*)(xout + (size_t)n1 * D + wcol + 4) =
            make_float4(acc1[2].f.x, acc1[2].f.y, acc1[3].f.x, acc1[3].f.y);
    }
}

// ---------------- launch ----------------
extern "C" void kernel_launch(void* const* d_in, const int* in_sizes, int n_in,
                              void* d_out, int out_size) {
    const float* x   = (const float*)d_in[0];
    const int*   ei  = (const int*)d_in[1];     // int32 or int64 — detected at runtime
    const float* ew  = (const float*)d_in[2];
    const float* W10 = (const float*)d_in[3];
    const float* W20 = (const float*)d_in[4];
    const float* W11 = (const float*)d_in[5];
    const float* W21 = (const float*)d_in[6];
    float* out = (float*)d_out;
    (void)in_sizes; (void)n_in; (void)out_size;

    float *buf1, *w1t0, *w2t0;
    cudaGetSymbolAddress((void**)&buf1, g_buf1);
    cudaGetSymbolAddress((void**)&w1t0, g_W1T);
    cudaGetSymbolAddress((void**)&w2t0, g_W2T);
    float* w1t1 = w1t0 + D * D;
    float* w2t1 = w2t0 + D * D;

    const int SMEM_BYTES = (2 * D * D + NB * SP) * (int)sizeof(float);  // 50176
    cudaFuncSetAttribute(k_layer<false>, cudaFuncAttributeMaxDynamicSharedMemorySize, SMEM_BYTES);
    cudaFuncSetAttribute(k_layer<true >, cudaFuncAttributeMaxDynamicSharedMemorySize, SMEM_BYTES);

    const int TPB = 256;
    k_detect<<<1, 32>>>((const unsigned int*)ei);
    k_prep<<<(N_NODES + TPB - 1) / TPB, TPB>>>(W10, W20, W11, W21);
    k_hist<<<(N_EDGES + TPB - 1) / TPB, TPB>>>(ei);
    k_scan1<<<NBLK_SCAN, 1024>>>();
    k_scan2<<<1, 64>>>();
    k_scan3<<<NBLK_SCAN, 1024>>>();
    k_scatter<<<(N_EDGES + TPB - 1) / TPB, TPB>>>(ei, ew);

    int grid = (N_NODES + NB - 1) / NB;
    k_layer<false><<<grid, 256, SMEM_BYTES>>>(x,    buf1, w1t0, w2t0);
    k_layer<true ><<<grid, 256, SMEM_BYTES>>>(buf1, out,  w1t1, w2t1);
}

// round 16
// speedup vs baseline: 1.0085x; 1.0085x over previous
#include <cuda_runtime.h>
#include <cuda_bf16.h>

#define N_NODES 50000
#define N_EDGES 800000
#define D 64
#define NB 64                 // nodes per layer-block
#define SP 68                 // shared activation row pitch (floats)
#define NBLK_SCAN ((N_NODES + 1023) / 1024)   // 49

// ---------------- device scratch (no allocation allowed) ----------------
__device__ int   g_is64;
__device__ int   g_count[N_NODES];
__device__ int   g_off[N_NODES + 1];
__device__ int   g_cursor[N_NODES];
__device__ int   g_bsum[NBLK_SCAN];
__device__ int2  g_edge[N_EDGES];         // (src, weight-as-int), sorted by dst
__device__ float g_buf1[N_NODES * D];
__device__ float g_W1T[2][D * D];
__device__ float g_W2T[2][D * D];

// ---------------- packed f32x2 FMA (sm_103a) with scalar fallback ----------------
union F2 { unsigned long long u; float2 f; };

__device__ __forceinline__ unsigned long long ffma2u(unsigned long long a,
                                                     unsigned long long b,
                                                     unsigned long long c) {
#if defined(__CUDA_ARCH__) && (__CUDA_ARCH__ >= 1000)
    unsigned long long d;
    asm("fma.rn.f32x2 %0, %1, %2, %3;" : "=l"(d) : "l"(a), "l"(b), "l"(c));
    return d;
#else
    F2 fa, fb, fc, fd;
    fa.u = a; fb.u = b; fc.u = c;
    fd.f.x = fmaf(fa.f.x, fb.f.x, fc.f.x);
    fd.f.y = fmaf(fa.f.y, fb.f.y, fc.f.y);
    return fd.u;
#endif
}

__device__ __forceinline__ int load_idx(const int* __restrict__ ei, long long pos, int is64) {
    int v;
    if (is64) v = (int)((const long long*)ei)[pos];
    else      v = ei[pos];
    v = v < 0 ? 0 : (v >= N_NODES ? N_NODES - 1 : v);
    return v;
}

// ---------------- prep: dtype detect + zero counts + transpose weights ----------------
__global__ void k_prep(const float* __restrict__ W10, const float* __restrict__ W20,
                       const float* __restrict__ W11, const float* __restrict__ W21,
                       const unsigned int* __restrict__ ei32) {
    int i = blockIdx.x * blockDim.x + threadIdx.x;
    if (i == 0) {
        unsigned int nz = 0;
        #pragma unroll
        for (int j = 0; j < 64; j++) nz |= ei32[2 * j + 1];
        g_is64 = (nz == 0u) ? 1 : 0;
    }
    if (i < N_NODES) g_count[i] = 0;
    if (i < D * D) {
        int o = i / D, k = i % D;
        g_W1T[0][k * D + o] = W10[i];
        g_W2T[0][k * D + o] = W20[i];
        g_W1T[1][k * D + o] = W11[i];
        g_W2T[1][k * D + o] = W21[i];
    }
}

// ---------------- CSR build ----------------
__global__ void k_hist(const int* __restrict__ ei) {
    int e = blockIdx.x * blockDim.x + threadIdx.x;
    if (e < N_EDGES) {
        int is64 = g_is64;
        int d = load_idx(ei, (long long)N_EDGES + e, is64);
        atomicAdd(&g_count[d], 1);
    }
}

// scan stage 1: per-block inclusive scan via warp shuffles (2 barriers, not 20)
__global__ void k_scan1() {
    __shared__ int wsum[32];
    int t = threadIdx.x, b = blockIdx.x;
    int lane = t & 31, warp = t >> 5;
    int i = b * 1024 + t;
    int v = (i < N_NODES) ? g_count[i] : 0;
    int x = v;
    #pragma unroll
    for (int ofs = 1; ofs < 32; ofs <<= 1) {
        int u = __shfl_up_sync(0xffffffffu, x, ofs);
        if (lane >= ofs) x += u;
    }
    if (lane == 31) wsum[warp] = x;
    __syncthreads();
    if (warp == 0) {
        int s = wsum[lane];
        #pragma unroll
        for (int ofs = 1; ofs < 32; ofs <<= 1) {
            int u = __shfl_up_sync(0xffffffffu, s, ofs);
            if (lane >= ofs) s += u;
        }
        wsum[lane] = s;
    }
    __syncthreads();
    int incl = x + (warp ? wsum[warp - 1] : 0);
    if (i < N_NODES) g_cursor[i] = incl;
    if (t == 1023) g_bsum[b] = incl;
}

// scan stages 2+3 merged: each block redundantly scans the 49 block sums,
// then applies its exclusive prefix and finalizes offsets + cursors.
__global__ void k_scan23() {
    __shared__ int sums[64];
    int t = threadIdx.x, b = blockIdx.x;
    if (t < 64) sums[t] = (t < NBLK_SCAN) ? g_bsum[t] : 0;
    __syncthreads();
    #pragma unroll
    for (int ofs = 1; ofs < 64; ofs <<= 1) {
        int u = 0;
        if (t < 64 && t >= ofs) u = sums[t - ofs];
        __syncthreads();
        if (t < 64) sums[t] += u;
        __syncthreads();
    }
    int pre = (b > 0) ? sums[b - 1] : 0;   // exclusive prefix of this block
    int i = b * 1024 + t;
    if (i < N_NODES) {
        int excl = pre + g_cursor[i] - g_count[i];
        g_off[i] = excl;
        g_cursor[i] = excl;
    }
    if (i == 0) g_off[N_NODES] = N_EDGES;
}

__global__ void k_scatter(const int* __restrict__ ei,
                          const float* __restrict__ w) {
    int e = blockIdx.x * blockDim.x + threadIdx.x;
    if (e < N_EDGES) {
        int is64 = g_is64;
        int d = load_idx(ei, (long long)N_EDGES + e, is64);
        int s = load_idx(ei, e, is64);
        int p = atomicAdd(&g_cursor[d], 1);
        g_edge[p] = make_int2(s, __float_as_int(w[e]));
    }
}

// ---------------- fused GIN layer ----------------
// Block = 256 threads, NB = 64 nodes, 4 blocks/SM enforced.
// Phase A: 8 warps x 8 nodes; x8 edge unroll (8 independent x-row loads in flight).
// Phase B: FFMA2 MLP, 2 nodes x 8 features per thread; sA reused for h.
template <bool NORM>
__global__ void __launch_bounds__(256, 4) k_layer(const float* __restrict__ xin,
                                                  float* __restrict__ xout,
                                                  const float* __restrict__ W1T,
                                                  const float* __restrict__ W2T) {
    extern __shared__ float smem[];
    float* sW1 = smem;                  // 4096 floats
    float* sW2 = smem + 4096;           // 4096
    float* sA  = smem + 8192;           // NB*SP floats

    int tid = threadIdx.x;
    int base = blockIdx.x * NB;

    {
        const float4* w1 = (const float4*)W1T;
        const float4* w2 = (const float4*)W2T;
        float4* s1 = (float4*)sW1;
        float4* s2 = (float4*)sW2;
        #pragma unroll
        for (int i = tid; i < (D * D) / 4; i += 256) {
            s1[i] = w1[i];
            s2[i] = w2[i];
        }
    }

    // ---- Phase A: weighted gather-sum (x8 unroll -> MLP 8) ----
    {
        int warp = tid >> 5;
        int lane = tid & 31;
        const float* xp = xin + (size_t)lane * 2;
        #pragma unroll 1
        for (int n = 0; n < 8; n++) {
            int ln = warp * 8 + n;
            int node = base + ln;
            float a0 = 0.f, a1 = 0.f;
            if (node < N_NODES) {
                int beg = g_off[node];
                int end = g_off[node + 1];
                int e = beg;
                for (; e + 8 <= end; e += 8) {
                    int2 ed[8];
                    #pragma unroll
                    for (int j = 0; j < 8; j++) ed[j] = g_edge[e + j];
                    float2 xv[8];
                    #pragma unroll
                    for (int j = 0; j < 8; j++)
                        xv[j] = *(const float2*)(xp + (size_t)ed[j].x * D);
                    #pragma unroll
                    for (int j = 0; j < 8; j++) {
                        float wv = __int_as_float(ed[j].y);
                        a0 += wv * xv[j].x;
                        a1 += wv * xv[j].y;
                    }
                }
                for (; e + 4 <= end; e += 4) {
                    int2 ed[4];
                    #pragma unroll
                    for (int j = 0; j < 4; j++) ed[j] = g_edge[e + j];
                    float2 xv[4];
                    #pragma unroll
                    for (int j = 0; j < 4; j++)
                        xv[j] = *(const float2*)(xp + (size_t)ed[j].x * D);
                    #pragma unroll
                    for (int j = 0; j < 4; j++) {
                        float wv = __int_as_float(ed[j].y);
                        a0 += wv * xv[j].x;
                        a1 += wv * xv[j].y;
                    }
                }
                for (; e < end; e++) {
                    int2 ed = g_edge[e];
                    float2 xv = *(const float2*)(xp + (size_t)ed.x * D);
                    a0 += __int_as_float(ed.y) * xv.x;
                    a1 += __int_as_float(ed.y) * xv.y;
                }
            }
            *(float2*)(sA + ln * SP + lane * 2) = make_float2(a0, a1);
        }
    }
    __syncthreads();

    // ---- Phase B: FFMA2-tiled MLP (2 nodes x 8 features per thread) ----
    int tg = tid >> 3;
    int tt = tid & 7;
    int rowA = 2 * tg * SP;
    int wcol = tt * 8;

    F2 acc0[4], acc1[4];
    #pragma unroll
    for (int p = 0; p < 4; p++) { acc0[p].u = 0ull; acc1[p].u = 0ull; }

    #pragma unroll 8
    for (int k = 0; k < D; k++) {
        float a0 = sA[rowA + k];
        float a1 = sA[rowA + SP + k];
        F2 as0, as1;
        as0.f = make_float2(a0, a0);
        as1.f = make_float2(a1, a1);
        float4 w0 = *(const float4*)(sW1 + k * D + wcol);
        float4 w1 = *(const float4*)(sW1 + k * D + wcol + 4);
        F2 wp0, wp1, wp2, wp3;
        wp0.f = make_float2(w0.x, w0.y);
        wp1.f = make_float2(w0.z, w0.w);
        wp2.f = make_float2(w1.x, w1.y);
        wp3.f = make_float2(w1.z, w1.w);
        acc0[0].u = ffma2u(as0.u, wp0.u, acc0[0].u);
        acc0[1].u = ffma2u(as0.u, wp1.u, acc0[1].u);
        acc0[2].u = ffma2u(as0.u, wp2.u, acc0[2].u);
        acc0[3].u = ffma2u(as0.u, wp3.u, acc0[3].u);
        acc1[0].u = ffma2u(as1.u, wp0.u, acc1[0].u);
        acc1[1].u = ffma2u(as1.u, wp1.u, acc1[1].u);
        acc1[2].u = ffma2u(as1.u, wp2.u, acc1[2].u);
        acc1[3].u = ffma2u(as1.u, wp3.u, acc1[3].u);
    }

    __syncthreads();

    {
        float4 h0a = make_float4(fmaxf(acc0[0].f.x, 0.f), fmaxf(acc0[0].f.y, 0.f),
                                 fmaxf(acc0[1].f.x, 0.f), fmaxf(acc0[1].f.y, 0.f));
        float4 h0b = make_float4(fmaxf(acc0[2].f.x, 0.f), fmaxf(acc0[2].f.y, 0.f),
                                 fmaxf(acc0[3].f.x, 0.f), fmaxf(acc0[3].f.y, 0.f));
        float4 h1a = make_float4(fmaxf(acc1[0].f.x, 0.f), fmaxf(acc1[0].f.y, 0.f),
                                 fmaxf(acc1[1].f.x, 0.f), fmaxf(acc1[1].f.y, 0.f));
        float4 h1b = make_float4(fmaxf(acc1[2].f.x, 0.f), fmaxf(acc1[2].f.y, 0.f),
                                 fmaxf(acc1[3].f.x, 0.f), fmaxf(acc1[3].f.y, 0.f));
        *(float4*)(sA + rowA + wcol)          = h0a;
        *(float4*)(sA + rowA + wcol + 4)      = h0b;
        *(float4*)(sA + rowA + SP + wcol)     = h1a;
        *(float4*)(sA + rowA + SP + wcol + 4) = h1b;
    }
    __syncthreads();

    #pragma unroll
    for (int p = 0; p < 4; p++) { acc0[p].u = 0ull; acc1[p].u = 0ull; }
    #pragma unroll 8
    for (int k = 0; k < D; k++) {
        float a0 = sA[rowA + k];
        float a1 = sA[rowA + SP + k];
        F2 as0, as1;
        as0.f = make_float2(a0, a0);
        as1.f = make_float2(a1, a1);
        float4 w0 = *(const float4*)(sW2 + k * D + wcol);
        float4 w1 = *(const float4*)(sW2 + k * D + wcol + 4);
        F2 wp0, wp1, wp2, wp3;
        wp0.f = make_float2(w0.x, w0.y);
        wp1.f = make_float2(w0.z, w0.w);
        wp2.f = make_float2(w1.x, w1.y);
        wp3.f = make_float2(w1.z, w1.w);
        acc0[0].u = ffma2u(as0.u, wp0.u, acc0[0].u);
        acc0[1].u = ffma2u(as0.u, wp1.u, acc0[1].u);
        acc0[2].u = ffma2u(as0.u, wp2.u, acc0[2].u);
        acc0[3].u = ffma2u(as0.u, wp3.u, acc0[3].u);
        acc1[0].u = ffma2u(as1.u, wp0.u, acc1[0].u);
        acc1[1].u = ffma2u(as1.u, wp1.u, acc1[1].u);
        acc1[2].u = ffma2u(as1.u, wp2.u, acc1[2].u);
        acc1[3].u = ffma2u(as1.u, wp3.u, acc1[3].u);
    }

    int n0 = base + 2 * tg;
    int n1 = n0 + 1;

    if (NORM) {
        float sq0 = acc0[0].f.x * acc0[0].f.x + acc0[0].f.y * acc0[0].f.y
                  + acc0[1].f.x * acc0[1].f.x + acc0[1].f.y * acc0[1].f.y
                  + acc0[2].f.x * acc0[2].f.x + acc0[2].f.y * acc0[2].f.y
                  + acc0[3].f.x * acc0[3].f.x + acc0[3].f.y * acc0[3].f.y;
        float sq1 = acc1[0].f.x * acc1[0].f.x + acc1[0].f.y * acc1[0].f.y
                  + acc1[1].f.x * acc1[1].f.x + acc1[1].f.y * acc1[1].f.y
                  + acc1[2].f.x * acc1[2].f.x + acc1[2].f.y * acc1[2].f.y
                  + acc1[3].f.x * acc1[3].f.x + acc1[3].f.y * acc1[3].f.y;
        #pragma unroll
        for (int m = 4; m > 0; m >>= 1) {
            sq0 += __shfl_xor_sync(0xffffffffu, sq0, m, 8);
            sq1 += __shfl_xor_sync(0xffffffffu, sq1, m, 8);
        }
        float inv0 = 1.f / fmaxf(sqrtf(sq0), 1e-12f);
        float inv1 = 1.f / fmaxf(sqrtf(sq1), 1e-12f);
        #pragma unroll
        for (int p = 0; p < 4; p++) {
            acc0[p].f.x *= inv0; acc0[p].f.y *= inv0;
            acc1[p].f.x *= inv1; acc1[p].f.y *= inv1;
        }
    }

    if (n0 < N_NODES) {
        *(float4*)(xout + (size_t)n0 * D + wcol) =
            make_float4(acc0[0].f.x, acc0[0].f.y, acc0[1].f.x, acc0[1].f.y);
        *(float4*)(xout + (size_t)n0 * D + wcol + 4) =
            make_float4(acc0[2].f.x, acc0[2].f.y, acc0[3].f.x, acc0[3].f.y);
    }
    if (n1 < N_NODES) {
        *(float4*)(xout + (size_t)n1 * D + wcol) =
            make_float4(acc1[0].f.x, acc1[0].f.y, acc1[1].f.x, acc1[1].f.y);
        *(float4*)(xout + (size_t)n1 * D + wcol + 4) =
            make_float4(acc1[2].f.x, acc1[2].f.y, acc1[3].f.x, acc1[3].f.y);
    }
}

// ---------------- launch ----------------
extern "C" void kernel_launch(void* const* d_in, const int* in_sizes, int n_in,
                              void* d_out, int out_size) {
    const float* x   = (const float*)d_in[0];
    const int*   ei  = (const int*)d_in[1];     // int32 or int64 — detected at runtime
    const float* ew  = (const float*)d_in[2];
    const float* W10 = (const float*)d_in[3];
    const float* W20 = (const float*)d_in[4];
    const float* W11 = (const float*)d_in[5];
    const float* W21 = (const float*)d_in[6];
    float* out = (float*)d_out;
    (void)in_sizes; (void)n_in; (void)out_size;

    float *buf1, *w1t0, *w2t0;
    cudaGetSymbolAddress((void**)&buf1, g_buf1);
    cudaGetSymbolAddress((void**)&w1t0, g_W1T);
    cudaGetSymbolAddress((void**)&w2t0, g_W2T);
    float* w1t1 = w1t0 + D * D;
    float* w2t1 = w2t0 + D * D;

    const int SMEM_BYTES = (2 * D * D + NB * SP) * (int)sizeof(float);  // 50176
    cudaFuncSetAttribute(k_layer<false>, cudaFuncAttributeMaxDynamicSharedMemorySize, SMEM_BYTES);
    cudaFuncSetAttribute(k_layer<true >, cudaFuncAttributeMaxDynamicSharedMemorySize, SMEM_BYTES);

    const int TPB = 256;
    k_prep<<<(N_NODES + TPB - 1) / TPB, TPB>>>(W10, W20, W11, W21, (const unsigned int*)ei);
    k_hist<<<(N_EDGES + TPB - 1) / TPB, TPB>>>(ei);
    k_scan1<<<NBLK_SCAN, 1024>>>();
    k_scan23<<<NBLK_SCAN, 1024>>>();
    k_scatter<<<(N_EDGES + TPB - 1) / TPB, TPB>>>(ei, ew);

    int grid = (N_NODES + NB - 1) / NB;
    k_layer<false><<<grid, 256, SMEM_BYTES>>>(x,    buf1, w1t0, w2t0);
    k_layer<true ><<<grid, 256, SMEM_BYTES>>>(buf1, out,  w1t1, w2t1);
}